// round 1
// baseline (speedup 1.0000x reference)
#include <cuda_runtime.h>
#include <math.h>

#define BATCH 64
#define SEQ   256
#define EDIM  300
#define HID   512
#define ATTD  256
#define NROWS (BATCH*SEQ)          // 16384

// ------------------------- scratch (static device memory) -------------------
__device__ float g_e[NROWS*EDIM];              // renormed embeddings  [16384,300]
__device__ float g_xw[2][NROWS*3*HID];         // input projections    [dir][16384,1536]
__device__ float g_h[NROWS*2*HID];             // concat hidden        [b,s,1024]
__device__ float g_state[2][2][BATCH*HID];     // [parity][dir][64,512]
__device__ float g_target[BATCH*2*HID];        // pooled target        [64,1024]
__device__ float g_tb[BATCH*ATTD];             // target@W1b + b1      [64,256]
__device__ float g_o[NROWS*ATTD];              // tanh attention feats [16384,256]
__device__ float g_alfa[BATCH*ATTD*SEQ];       // beta -> alfa         [64,256,256]
__device__ float g_att[NROWS*2*HID];           // result               [b*256+k,1024]

// ------------------------- helpers ------------------------------------------
__device__ __forceinline__ float warp_sum(float v) {
    #pragma unroll
    for (int o = 16; o > 0; o >>= 1) v += __shfl_xor_sync(0xffffffffu, v, o);
    return v;
}
__device__ __forceinline__ float warp_max(float v) {
    #pragma unroll
    for (int o = 16; o > 0; o >>= 1) v = fmaxf(v, __shfl_xor_sync(0xffffffffu, v, o));
    return v;
}

// ------------------------- K0: zero GRU state --------------------------------
__global__ void k_zero_state() {
    int i = blockIdx.x * blockDim.x + threadIdx.x;
    if (i < 2*2*BATCH*HID) ((float*)g_state)[i] = 0.f;
}

// ------------------------- K1: embedding gather + renorm ---------------------
// one warp per (b,s) row
__global__ void k_embed(const int* __restrict__ x, const float* __restrict__ emb) {
    int w = blockIdx.x * (blockDim.x >> 5) + (threadIdx.x >> 5);
    int lane = threadIdx.x & 31;
    if (w >= NROWS) return;
    const float* src = emb + (long)x[w] * EDIM;
    float v[10];
    float ss = 0.f;
    #pragma unroll
    for (int i = 0; i < 10; i++) {
        int c = lane + 32*i;
        float t = (c < EDIM) ? __ldg(src + c) : 0.f;
        v[i] = t; ss += t*t;
    }
    ss = warp_sum(ss);
    float sc = fminf(1.f, 5.f / (sqrtf(ss) + 1e-7f));
    float* dst = g_e + (long)w * EDIM;
    #pragma unroll
    for (int i = 0; i < 10; i++) {
        int c = lane + 32*i;
        if (c < EDIM) dst[c] = v[i] * sc;
    }
}

// ------------------------- generic fp32 tiled GEMMs --------------------------
// C[M,N] = A[M,K] . B[N,K]^T   (NT: dot of two K-major rows), 64x64 tile, 256 thr
// epi: 0 -> C = acc + bias[col]
//      1 -> C = tanh(acc + tb2[(row>>8)*256 + col])
//      2 -> C = acc
__global__ __launch_bounds__(256) void k_gemm_nt(
    const float* __restrict__ A, const float* __restrict__ B, float* __restrict__ C,
    int M, int N, int K, int lda, int ldb, int ldc,
    long sA, long sB, long sC,
    const float* __restrict__ bias, const float* __restrict__ tb2, int epi)
{
    __shared__ __align__(16) float As[16][64];
    __shared__ __align__(16) float Bs[16][64];
    int bz = blockIdx.z;
    A += sA * bz; B += sB * bz; C += sC * bz;
    int m0 = blockIdx.x << 6, n0 = blockIdx.y << 6;
    int tid = threadIdx.x;
    int tx = tid & 15, ty = tid >> 4;
    float acc[4][4] = {};
    for (int k0 = 0; k0 < K; k0 += 16) {
        int r = tid >> 2;
        int cb = (tid & 3) << 2;
        #pragma unroll
        for (int p = 0; p < 4; p++) {
            int c = cb + p;
            float va = 0.f, vb = 0.f;
            if (k0 + c < K) {
                va = A[(long)(m0 + r) * lda + k0 + c];
                vb = B[(long)(n0 + r) * ldb + k0 + c];
            }
            As[c][r] = va;
            Bs[c][r] = vb;
        }
        __syncthreads();
        #pragma unroll
        for (int k = 0; k < 16; k++) {
            float4 av = *(const float4*)&As[k][ty << 2];
            float4 bv = *(const float4*)&Bs[k][tx << 2];
            acc[0][0] = fmaf(av.x, bv.x, acc[0][0]);
            acc[0][1] = fmaf(av.x, bv.y, acc[0][1]);
            acc[0][2] = fmaf(av.x, bv.z, acc[0][2]);
            acc[0][3] = fmaf(av.x, bv.w, acc[0][3]);
            acc[1][0] = fmaf(av.y, bv.x, acc[1][0]);
            acc[1][1] = fmaf(av.y, bv.y, acc[1][1]);
            acc[1][2] = fmaf(av.y, bv.z, acc[1][2]);
            acc[1][3] = fmaf(av.y, bv.w, acc[1][3]);
            acc[2][0] = fmaf(av.z, bv.x, acc[2][0]);
            acc[2][1] = fmaf(av.z, bv.y, acc[2][1]);
            acc[2][2] = fmaf(av.z, bv.z, acc[2][2]);
            acc[2][3] = fmaf(av.z, bv.w, acc[2][3]);
            acc[3][0] = fmaf(av.w, bv.x, acc[3][0]);
            acc[3][1] = fmaf(av.w, bv.y, acc[3][1]);
            acc[3][2] = fmaf(av.w, bv.z, acc[3][2]);
            acc[3][3] = fmaf(av.w, bv.w, acc[3][3]);
        }
        __syncthreads();
    }
    #pragma unroll
    for (int i = 0; i < 4; i++) {
        int row = m0 + (ty << 2) + i;
        #pragma unroll
        for (int j = 0; j < 4; j++) {
            int col = n0 + (tx << 2) + j;
            float v = acc[i][j];
            if (epi == 0)      v += bias[col];
            else if (epi == 1) v = tanhf(v + tb2[((row >> 8) << 8) + col]);
            C[(long)row * ldc + col] = v;
        }
    }
}

// C[M,N] = A[M,K] . B[K,N]   (NN), 64x64 tile, 256 thr, plain epilogue
__global__ __launch_bounds__(256) void k_gemm_nn(
    const float* __restrict__ A, const float* __restrict__ B, float* __restrict__ C,
    int M, int N, int K, int lda, int ldb, int ldc,
    long sA, long sB, long sC)
{
    __shared__ __align__(16) float As[16][64];
    __shared__ __align__(16) float Bs[16][64];
    int bz = blockIdx.z;
    A += sA * bz; B += sB * bz; C += sC * bz;
    int m0 = blockIdx.x << 6, n0 = blockIdx.y << 6;
    int tid = threadIdx.x;
    int tx = tid & 15, ty = tid >> 4;
    float acc[4][4] = {};
    for (int k0 = 0; k0 < K; k0 += 16) {
        {   // A tile (transposed store)
            int r = tid >> 2;
            int cb = (tid & 3) << 2;
            #pragma unroll
            for (int p = 0; p < 4; p++) {
                int c = cb + p;
                float va = 0.f;
                if (k0 + c < K) va = A[(long)(m0 + r) * lda + k0 + c];
                As[c][r] = va;
            }
        }
        {   // B tile (direct: rows are k, cols coalesced)
            int kk = tid >> 4;
            int cb = (tid & 15) << 2;
            #pragma unroll
            for (int p = 0; p < 4; p++) {
                int c = cb + p;
                float vb = 0.f;
                if (k0 + kk < K) vb = B[(long)(k0 + kk) * ldb + n0 + c];
                Bs[kk][c] = vb;
            }
        }
        __syncthreads();
        #pragma unroll
        for (int k = 0; k < 16; k++) {
            float4 av = *(const float4*)&As[k][ty << 2];
            float4 bv = *(const float4*)&Bs[k][tx << 2];
            acc[0][0] = fmaf(av.x, bv.x, acc[0][0]);
            acc[0][1] = fmaf(av.x, bv.y, acc[0][1]);
            acc[0][2] = fmaf(av.x, bv.z, acc[0][2]);
            acc[0][3] = fmaf(av.x, bv.w, acc[0][3]);
            acc[1][0] = fmaf(av.y, bv.x, acc[1][0]);
            acc[1][1] = fmaf(av.y, bv.y, acc[1][1]);
            acc[1][2] = fmaf(av.y, bv.z, acc[1][2]);
            acc[1][3] = fmaf(av.y, bv.w, acc[1][3]);
            acc[2][0] = fmaf(av.z, bv.x, acc[2][0]);
            acc[2][1] = fmaf(av.z, bv.y, acc[2][1]);
            acc[2][2] = fmaf(av.z, bv.z, acc[2][2]);
            acc[2][3] = fmaf(av.z, bv.w, acc[2][3]);
            acc[3][0] = fmaf(av.w, bv.x, acc[3][0]);
            acc[3][1] = fmaf(av.w, bv.y, acc[3][1]);
            acc[3][2] = fmaf(av.w, bv.z, acc[3][2]);
            acc[3][3] = fmaf(av.w, bv.w, acc[3][3]);
        }
        __syncthreads();
    }
    #pragma unroll
    for (int i = 0; i < 4; i++) {
        int row = m0 + (ty << 2) + i;
        #pragma unroll
        for (int j = 0; j < 4; j++) {
            int col = n0 + (tx << 2) + j;
            C[(long)row * ldc + col] = acc[i][j];
        }
    }
}

// ------------------------- K4: fused GRU step --------------------------------
// 128 blocks = 2 dirs x 64 j-tiles (8 hidden units each), 256 threads.
// Each block: gh tile for all 64 batch rows (3 gates x 8 units), smem-staged
// W (24 rows) and h (64 rows) in 64-wide K chunks; fused gate nonlinearity +
// state update. Double-buffered state on parity of t.
#define KC 64
#define PAD 76
__global__ __launch_bounds__(256) void k_gru_step(
    const float* __restrict__ Wf, const float* __restrict__ Wb,
    const float* __restrict__ bf, const float* __restrict__ bb, int t)
{
    __shared__ __align__(16) float Ws[24][PAD];
    __shared__ __align__(16) float Hs[64][PAD];

    int blk = blockIdx.x;
    int dir = blk >> 6;
    int j0  = (blk & 63) << 3;
    int jt  = threadIdx.x & 7;
    int mg  = threadIdx.x >> 3;          // 0..31
    int m0  = mg << 1;

    const float* W  = dir ? Wb : Wf;
    const float* bh = dir ? bb : bf;
    const float* hp = g_state[t & 1][dir];
    float*       hn = g_state[(t + 1) & 1][dir];

    float ar0=0.f, ar1=0.f, az0=0.f, az1=0.f, an0=0.f, an1=0.f;

    for (int k0 = 0; k0 < HID; k0 += KC) {
        // stage W: 24 rows x 64 k = 384 float4
        #pragma unroll
        for (int p = 0; p < 2; p++) {
            int l4 = threadIdx.x + (p << 8);
            if (l4 < 384) {
                int r  = l4 >> 4;            // 0..23
                int c4 = l4 & 15;
                int wrow = ((r >> 3) << 9) + j0 + (r & 7);   // gate*512 + j
                float4 v = *(const float4*)&W[(long)wrow * HID + k0 + (c4 << 2)];
                *(float4*)&Ws[r][c4 << 2] = v;
            }
        }
        // stage h: 64 rows x 64 k = 1024 float4 (4 per thread)
        #pragma unroll
        for (int p = 0; p < 4; p++) {
            int l4 = threadIdx.x + (p << 8);
            int r  = l4 >> 4;                // 0..63
            int c4 = l4 & 15;
            float4 v = *(const float4*)&hp[(long)r * HID + k0 + (c4 << 2)];
            *(float4*)&Hs[r][c4 << 2] = v;
        }
        __syncthreads();
        #pragma unroll
        for (int k = 0; k < KC; k += 4) {
            float4 wr = *(const float4*)&Ws[jt][k];
            float4 wz = *(const float4*)&Ws[8 + jt][k];
            float4 wn = *(const float4*)&Ws[16 + jt][k];
            float4 ha = *(const float4*)&Hs[m0][k];
            float4 hb = *(const float4*)&Hs[m0 + 1][k];
            ar0 = fmaf(wr.x, ha.x, ar0); ar0 = fmaf(wr.y, ha.y, ar0);
            ar0 = fmaf(wr.z, ha.z, ar0); ar0 = fmaf(wr.w, ha.w, ar0);
            az0 = fmaf(wz.x, ha.x, az0); az0 = fmaf(wz.y, ha.y, az0);
            az0 = fmaf(wz.z, ha.z, az0); az0 = fmaf(wz.w, ha.w, az0);
            an0 = fmaf(wn.x, ha.x, an0); an0 = fmaf(wn.y, ha.y, an0);
            an0 = fmaf(wn.z, ha.z, an0); an0 = fmaf(wn.w, ha.w, an0);
            ar1 = fmaf(wr.x, hb.x, ar1); ar1 = fmaf(wr.y, hb.y, ar1);
            ar1 = fmaf(wr.z, hb.z, ar1); ar1 = fmaf(wr.w, hb.w, ar1);
            az1 = fmaf(wz.x, hb.x, az1); az1 = fmaf(wz.y, hb.y, az1);
            az1 = fmaf(wz.z, hb.z, az1); az1 = fmaf(wz.w, hb.w, az1);
            an1 = fmaf(wn.x, hb.x, an1); an1 = fmaf(wn.y, hb.y, an1);
            an1 = fmaf(wn.z, hb.z, an1); an1 = fmaf(wn.w, hb.w, an1);
        }
        __syncthreads();
    }

    int j  = j0 + jt;
    int tt = dir ? (SEQ - 1 - t) : t;
    float br = bh[j], bz2 = bh[HID + j], bn = bh[2 * HID + j];
    #pragma unroll
    for (int q = 0; q < 2; q++) {
        int m = m0 + q;
        float gr = (q ? ar1 : ar0) + br;
        float gz = (q ? az1 : az0) + bz2;
        float gn = (q ? an1 : an0) + bn;
        long row = (long)m * SEQ + tt;
        const float* xwrow = g_xw[dir] + row * (3 * HID);
        float r = 1.f / (1.f + expf(-(xwrow[j] + gr)));
        float z = 1.f / (1.f + expf(-(xwrow[HID + j] + gz)));
        float n = tanhf(xwrow[2 * HID + j] + r * gn);
        float hv = (1.f - z) * n + z * hp[m * HID + j];
        hn[m * HID + j] = hv;
        g_h[row * (2 * HID) + dir * HID + j] = hv;
    }
}

// ------------------------- K5: masked mean pooling ---------------------------
__global__ void k_pool(const int* __restrict__ ts, const int* __restrict__ te) {
    int b = blockIdx.x;
    int s0 = ts[b], s1 = te[b];
    float inv = 1.f / (float)(s1 - s0 + 1);
    for (int c = threadIdx.x; c < 2 * HID; c += blockDim.x) {
        float a = 0.f;
        for (int s = s0; s <= s1; s++)
            a += g_h[((long)b * SEQ + s) * (2 * HID) + c];
        g_target[b * 2 * HID + c] = a * inv;
    }
}

// ------------------------- K8b: row softmax over S ---------------------------
__global__ void k_softmax() {
    int row = blockIdx.x * (blockDim.x >> 5) + (threadIdx.x >> 5);
    int lane = threadIdx.x & 31;
    float* p = g_alfa + (long)row * SEQ;
    float v[8];
    float mx = -1e30f;
    #pragma unroll
    for (int i = 0; i < 8; i++) { v[i] = p[lane + 32 * i]; mx = fmaxf(mx, v[i]); }
    mx = warp_max(mx);
    float s = 0.f;
    #pragma unroll
    for (int i = 0; i < 8; i++) { v[i] = expf(v[i] - mx); s += v[i]; }
    s = warp_sum(s);
    float inv = 1.f / s;
    #pragma unroll
    for (int i = 0; i < 8; i++) p[lane + 32 * i] = v[i] * inv;
}

// ------------------------- K10: result @ W2^T + b2 ---------------------------
__global__ void k_final(const float* __restrict__ W2, const float* __restrict__ b2,
                        float* __restrict__ out) {
    int row = blockIdx.x * 8 + (threadIdx.x >> 5);
    int lane = threadIdx.x & 31;
    const float* R = g_att + (long)row * (2 * HID);
    float a0 = 0.f, a1 = 0.f, a2 = 0.f;
    for (int h = lane; h < 2 * HID; h += 32) {
        float r = R[h];
        a0 = fmaf(r, W2[h],            a0);
        a1 = fmaf(r, W2[2 * HID + h],  a1);
        a2 = fmaf(r, W2[4 * HID + h],  a2);
    }
    a0 = warp_sum(a0); a1 = warp_sum(a1); a2 = warp_sum(a2);
    if (lane == 0) {
        out[row * 3 + 0] = a0 + b2[0];
        out[row * 3 + 1] = a1 + b2[1];
        out[row * 3 + 2] = a2 + b2[2];
    }
}

// ------------------------- launcher ------------------------------------------
extern "C" void kernel_launch(void* const* d_in, const int* in_sizes, int n_in,
                              void* d_out, int out_size) {
    const int*   x      = (const int*)  d_in[0];
    const int*   tstart = (const int*)  d_in[1];
    const int*   tend   = (const int*)  d_in[2];
    const float* emb    = (const float*)d_in[3];
    const float* Wih_f  = (const float*)d_in[4];
    const float* Whh_f  = (const float*)d_in[5];
    const float* bih_f  = (const float*)d_in[6];
    const float* bhh_f  = (const float*)d_in[7];
    const float* Wih_b  = (const float*)d_in[8];
    const float* Whh_b  = (const float*)d_in[9];
    const float* bih_b  = (const float*)d_in[10];
    const float* bhh_b  = (const float*)d_in[11];
    const float* W1     = (const float*)d_in[12];
    const float* b1     = (const float*)d_in[13];
    const float* u      = (const float*)d_in[14];
    const float* W2     = (const float*)d_in[15];
    const float* b2     = (const float*)d_in[16];
    float* out = (float*)d_out;

    float *p_e, *p_xw, *p_h, *p_target, *p_tb, *p_o, *p_alfa, *p_att;
    cudaGetSymbolAddress((void**)&p_e,      g_e);
    cudaGetSymbolAddress((void**)&p_xw,     g_xw);
    cudaGetSymbolAddress((void**)&p_h,      g_h);
    cudaGetSymbolAddress((void**)&p_target, g_target);
    cudaGetSymbolAddress((void**)&p_tb,     g_tb);
    cudaGetSymbolAddress((void**)&p_o,      g_o);
    cudaGetSymbolAddress((void**)&p_alfa,   g_alfa);
    cudaGetSymbolAddress((void**)&p_att,    g_att);
    float* p_xw0 = p_xw;
    float* p_xw1 = p_xw + (long)NROWS * 3 * HID;

    k_zero_state<<<512, 256>>>();
    k_embed<<<2048, 256>>>(x, emb);

    // input projections: [16384,300] x [1536,300]^T (+bih)
    k_gemm_nt<<<dim3(256, 24, 1), 256>>>(p_e, Wih_f, p_xw0, NROWS, 3 * HID, EDIM,
                                         EDIM, EDIM, 3 * HID, 0, 0, 0,
                                         bih_f, nullptr, 0);
    k_gemm_nt<<<dim3(256, 24, 1), 256>>>(p_e, Wih_b, p_xw1, NROWS, 3 * HID, EDIM,
                                         EDIM, EDIM, 3 * HID, 0, 0, 0,
                                         bih_b, nullptr, 0);

    // recurrence: 256 fused steps, both directions per launch
    for (int t = 0; t < SEQ; t++)
        k_gru_step<<<128, 256>>>(Whh_f, Whh_b, bhh_f, bhh_b, t);

    // masked mean pool over target span
    k_pool<<<64, 256>>>(tstart, tend);

    // tb[b,a] = target[b] . W1[:,1024:]^T + b1   (M=64,N=256,K=1024)
    k_gemm_nt<<<dim3(1, 4, 1), 256>>>(p_target, W1 + 1024, p_tb, 64, ATTD, 2 * HID,
                                      2 * HID, 4 * HID, ATTD, 0, 0, 0,
                                      b1, nullptr, 0);

    // o = tanh(h . W1[:, :1024]^T + tb[b])       (M=16384,N=256,K=1024)
    k_gemm_nt<<<dim3(256, 4, 1), 256>>>(p_h, W1, p_o, NROWS, ATTD, 2 * HID,
                                        2 * HID, 4 * HID, ATTD, 0, 0, 0,
                                        nullptr, p_tb, 1);

    // beta[b,k,s] = u[k] . o[b,s]                (batched NT, M=N=K=256)
    k_gemm_nt<<<dim3(4, 4, 64), 256>>>(u, p_o, p_alfa, ATTD, SEQ, ATTD,
                                       ATTD, ATTD, SEQ,
                                       0, (long)SEQ * ATTD, (long)ATTD * SEQ,
                                       nullptr, nullptr, 2);

    // softmax over s
    k_softmax<<<2048, 256>>>();

    // result[b,k,:] = alfa[b,k,:] . h[b]         (batched NN, 256x1024x256)
    k_gemm_nn<<<dim3(4, 16, 64), 256>>>(p_alfa, p_h, p_att, ATTD, 2 * HID, SEQ,
                                        SEQ, 2 * HID, 2 * HID,
                                        (long)ATTD * SEQ, (long)SEQ * 2 * HID,
                                        (long)ATTD * 2 * HID);

    // final projection to 3 labels
    k_final<<<2048, 256>>>(W2, b2, out);
}